// round 3
// baseline (speedup 1.0000x reference)
#include <cuda_runtime.h>
#include <stdint.h>

#define NBINS 29
#define DDIM  4096
#define CDIM  4
#define QDIM  32
#define NWARP 8

// One block per (b,q). Mask is word-packed (established R2: rel_err==0 via the
// runtime probe; {0,1} or {0f,1f} words — we only test !=0). Loads the mask row
// once, streams the 4 c-slices of simmat with front-batched LDG.128s for high
// MLP, builds per-warp integer histograms in shared memory, reduces to float.
__global__ __launch_bounds__(256)
void count_hist_kernel(const float* __restrict__ sim,
                       const uint4* __restrict__ mask,
                       float* __restrict__ out)
{
    // [c][warp][bin] ; bins padded 29 -> 32 (bin == bank)
    __shared__ int hist[CDIM][NWARP][32];

    const int t    = threadIdx.x;
    const int warp = t >> 5;
    const int bq   = blockIdx.x;           // 0 .. B*Q-1
    const int b    = bq / QDIM;
    const int q    = bq - b * QDIM;

    #pragma unroll
    for (int i = t; i < CDIM * NWARP * 32; i += 256)
        (&hist[0][0][0])[i] = 0;
    __syncthreads();

    // sim row for (b, c=0, q); c-stride in float4 units:
    const float4* __restrict__ s4 =
        reinterpret_cast<const float4*>(sim + ((size_t)b * CDIM * QDIM + q) * DDIM);
    const int cStride4 = QDIM * DDIM / 4;

    const uint4* __restrict__ m4 = mask + (size_t)bq * (DDIM / 4);

    // 1024 float4 per row, 256 threads -> 4 indices/thread; process 2 per
    // macro-iter with ALL loads issued up front (2 mask + 8 sim LDG.128).
    #pragma unroll
    for (int k0 = 0; k0 < 4; k0 += 2) {
        const int i0 = k0 * 256 + t;
        const int i1 = i0 + 256;

        const uint4 ma = m4[i0];
        const uint4 mb = m4[i1];

        float4 sa[CDIM], sb[CDIM];
        #pragma unroll
        for (int c = 0; c < CDIM; ++c) {
            sa[c] = s4[c * cStride4 + i0];
            sb[c] = s4[c * cStride4 + i1];
        }

        #pragma unroll
        for (int c = 0; c < CDIM; ++c) {
            // (int)((x + 1.00001f) * 14.0f) == trunc(((x+1.00001f)/2)*28) bit-exact
            {
                const float4 s = sa[c];
                const int b0 = (int)((s.x + 1.00001f) * 14.0f);
                const int b1 = (int)((s.y + 1.00001f) * 14.0f);
                const int b2 = (int)((s.z + 1.00001f) * 14.0f);
                const int b3 = (int)((s.w + 1.00001f) * 14.0f);
                if (ma.x) atomicAdd(&hist[c][warp][b0], 1);
                if (ma.y) atomicAdd(&hist[c][warp][b1], 1);
                if (ma.z) atomicAdd(&hist[c][warp][b2], 1);
                if (ma.w) atomicAdd(&hist[c][warp][b3], 1);
            }
            {
                const float4 s = sb[c];
                const int b0 = (int)((s.x + 1.00001f) * 14.0f);
                const int b1 = (int)((s.y + 1.00001f) * 14.0f);
                const int b2 = (int)((s.z + 1.00001f) * 14.0f);
                const int b3 = (int)((s.w + 1.00001f) * 14.0f);
                if (mb.x) atomicAdd(&hist[c][warp][b0], 1);
                if (mb.y) atomicAdd(&hist[c][warp][b1], 1);
                if (mb.z) atomicAdd(&hist[c][warp][b2], 1);
                if (mb.w) atomicAdd(&hist[c][warp][b3], 1);
            }
        }
    }
    __syncthreads();

    // reduce 8 warp-copies and write: C*NBINS = 116 outputs per block
    if (t < CDIM * NBINS) {
        const int c   = t / NBINS;
        const int bin = t - c * NBINS;
        int sum = 0;
        #pragma unroll
        for (int w = 0; w < NWARP; ++w) sum += hist[c][w][bin];
        out[(((size_t)b * CDIM + c) * QDIM + q) * NBINS + bin] = (float)sum;
    }
}

extern "C" void kernel_launch(void* const* d_in, const int* in_sizes, int n_in,
                              void* d_out, int out_size)
{
    // sim is 4x larger (element count) than mask; pick by size for robustness.
    int i_sim  = 0, i_mask = 1;
    if (n_in >= 2 && in_sizes[1] > in_sizes[0]) { i_sim = 1; i_mask = 0; }

    const float* sim  = (const float*)d_in[i_sim];    // [B, C, Q, D] float32
    const uint4* mask = (const uint4*)d_in[i_mask];   // [B, Q, D] word-packed bool
    float*       out  = (float*)d_out;                // [B, C, Q, NBINS] float32

    const int blocks = in_sizes[i_mask] / DDIM;       // B*Q = 2048

    count_hist_kernel<<<blocks, 256>>>(sim, mask, out);
}

// round 4
// speedup vs baseline: 1.2860x; 1.2860x over previous
#include <cuda_runtime.h>
#include <stdint.h>

#define NBINS 29
#define DDIM  4096
#define CDIM  4
#define QDIM  32
#define NWARP 8

// One block per (b,q). Mask is word-packed 0/1 words (established R2/R3:
// rel_err == 0.0 with word interpretation). Loads the mask row once, streams
// the 4 c-slices of simmat, builds per-warp integer histograms in shared
// memory, reduces to float output. __launch_bounds__(256,8) pins regs<=32 so
// 8 blocks/SM (64 warps) — R3 showed occupancy beats deeper load batching.
__global__ __launch_bounds__(256, 8)
void count_hist_kernel(const float* __restrict__ sim,
                       const uint4* __restrict__ mask,
                       float* __restrict__ out)
{
    // [c][warp][bin] ; bins padded 29 -> 32 (bin == bank)
    __shared__ int hist[CDIM][NWARP][32];

    const int t    = threadIdx.x;
    const int warp = t >> 5;
    const int bq   = blockIdx.x;           // 0 .. B*Q-1
    const int b    = bq / QDIM;
    const int q    = bq - b * QDIM;

    #pragma unroll
    for (int i = t; i < CDIM * NWARP * 32; i += 256)
        (&hist[0][0][0])[i] = 0;
    __syncthreads();

    // sim row for (b, c=0, q); c-stride in float4 units:
    const float4* __restrict__ s4 =
        reinterpret_cast<const float4*>(sim + ((size_t)b * CDIM * QDIM + q) * DDIM);
    const int cStride4 = QDIM * DDIM / 4;

    const uint4* __restrict__ m4 = mask + (size_t)bq * (DDIM / 4);

    // 4096 elems = 1024 groups of 4 per row; 256 threads -> 4 iterations
    #pragma unroll
    for (int it = 0; it < 4; ++it) {
        const int idx = it * 256 + t;

        const uint4 m = m4[idx];            // 4 words = 4 mask elements (0/1)
        const int mx = (m.x != 0u), my = (m.y != 0u);
        const int mz = (m.z != 0u), mw = (m.w != 0u);

        #pragma unroll
        for (int c = 0; c < CDIM; ++c) {
            const float4 s = s4[c * cStride4 + idx];
            // (int)((x + 1.00001f) * 14.0f) == trunc(((x+1.00001f)/2)*28) bit-exact
            const int b0 = (int)((s.x + 1.00001f) * 14.0f);
            const int b1 = (int)((s.y + 1.00001f) * 14.0f);
            const int b2 = (int)((s.z + 1.00001f) * 14.0f);
            const int b3 = (int)((s.w + 1.00001f) * 14.0f);
            if (mx) atomicAdd(&hist[c][warp][b0], 1);
            if (my) atomicAdd(&hist[c][warp][b1], 1);
            if (mz) atomicAdd(&hist[c][warp][b2], 1);
            if (mw) atomicAdd(&hist[c][warp][b3], 1);
        }
    }
    __syncthreads();

    // reduce 8 warp-copies and write: C*NBINS = 116 outputs per block
    if (t < CDIM * NBINS) {
        const int c   = t / NBINS;
        const int bin = t - c * NBINS;
        int sum = 0;
        #pragma unroll
        for (int w = 0; w < NWARP; ++w) sum += hist[c][w][bin];
        out[(((size_t)b * CDIM + c) * QDIM + q) * NBINS + bin] = (float)sum;
    }
}

extern "C" void kernel_launch(void* const* d_in, const int* in_sizes, int n_in,
                              void* d_out, int out_size)
{
    // sim is 4x larger (element count) than mask; pick by size for robustness.
    int i_sim  = 0, i_mask = 1;
    if (n_in >= 2 && in_sizes[1] > in_sizes[0]) { i_sim = 1; i_mask = 0; }

    const float* sim  = (const float*)d_in[i_sim];    // [B, C, Q, D] float32
    const uint4* mask = (const uint4*)d_in[i_mask];   // [B, Q, D] word-packed bool
    float*       out  = (float*)d_out;                // [B, C, Q, NBINS] float32

    const int blocks = in_sizes[i_mask] / DDIM;       // B*Q = 2048

    count_hist_kernel<<<blocks, 256>>>(sim, mask, out);
}

// round 5
// speedup vs baseline: 1.3268x; 1.0318x over previous
#include <cuda_runtime.h>
#include <stdint.h>

#define NBINS 29
#define DDIM  4096
#define CDIM  4
#define QDIM  32
#define NWARP 8
#define NSLOT 5          // ring slots per warp (prefetch distance 4)
#define NSLICE 20        // per block: 4 iters x (1 mask + 4 sim) slices

__device__ __forceinline__ void cp_async16(uint32_t saddr, const void* gaddr) {
    asm volatile("cp.async.cg.shared.global [%0], [%1], 16;\n"
                 :: "r"(saddr), "l"(gaddr) : "memory");
}
#define CP_COMMIT() asm volatile("cp.async.commit_group;\n" ::: "memory")
#define CP_WAIT(N)  asm volatile("cp.async.wait_group %0;\n" :: "n"(N) : "memory")

// One block per (b,q). Mask is word-packed 0/1 (established R2-R4, rel_err==0).
// cp.async stages mask+sim slices through per-warp smem rings: deep MLP with
// no register cost (R3 showed reg-batched loads kill occupancy). Per-warp
// integer histograms in shared memory, reduced to float at the end.
__global__ __launch_bounds__(256, 8)
void count_hist_kernel(const float* __restrict__ sim,
                       const uint4* __restrict__ mask,
                       float* __restrict__ out)
{
    __shared__ int   hist[CDIM][NWARP][32];     // bin == bank (29 -> 32 pad)
    __shared__ uint4 ring[NWARP][NSLOT][32];    // 512B slices, per-warp private

    const int t    = threadIdx.x;
    const int warp = t >> 5;
    const int lane = t & 31;
    const int bq   = blockIdx.x;                // 0 .. B*Q-1
    const int b    = bq / QDIM;
    const int q    = bq - b * QDIM;

    #pragma unroll
    for (int i = t; i < CDIM * NWARP * 32; i += 256)
        (&hist[0][0][0])[i] = 0;
    __syncthreads();

    // Per-thread global bases (float4 / uint4 units), offset warp*32+lane.
    const uint4* __restrict__ gm =
        mask + (size_t)bq * (DDIM / 4) + warp * 32 + lane;
    const float4* __restrict__ gs =
        reinterpret_cast<const float4*>(sim + ((size_t)b * CDIM * QDIM + q) * DDIM)
        + warp * 32 + lane;
    const int cStride4 = QDIM * DDIM / 4;       // 32768

    // smem address of this thread's slot-0 cell; slot stride = 512 bytes.
    const uint32_t rl =
        (uint32_t)__cvta_generic_to_shared(&ring[warp][0][lane]);

    // slice j (0..19): it = j/5, k = j%5. k==0 -> mask; k>=1 -> sim c=k-1.
    // gmem elem offset (vec units) = it*256.
    // Prologue: slices 0..3 in flight.
    #pragma unroll
    for (int j = 0; j < 4; ++j) {
        const int it = j / 5, k = j % 5;
        const void* g = (k == 0) ? (const void*)(gm + it * 256)
                                 : (const void*)(gs + (k - 1) * cStride4 + it * 256);
        cp_async16(rl + (j % NSLOT) * 512, g);
        CP_COMMIT();
    }

    uint4 m;  // mask quad for the current iter (4 elements of this thread)

    #pragma unroll
    for (int j = 0; j < NSLICE; ++j) {
        const int slot = j % NSLOT;

        // Wait for slice j: allow min(3, 19-j) newer groups to stay pending.
        if      (NSLICE - 1 - j >= 3) CP_WAIT(3);
        else if (NSLICE - 1 - j == 2) CP_WAIT(2);
        else if (NSLICE - 1 - j == 1) CP_WAIT(1);
        else                          CP_WAIT(0);

        if ((j % 5) == 0) {
            m = ring[warp][slot][lane];         // park mask in regs for 4 slices
        } else {
            const int c = (j % 5) - 1;
            const float4 s =
                *reinterpret_cast<const float4*>(&ring[warp][slot][lane]);
            // (int)((x + 1.00001f)*14.0f) == trunc(((x+1.00001f)/2)*28) bit-exact
            const int b0 = (int)((s.x + 1.00001f) * 14.0f);
            const int b1 = (int)((s.y + 1.00001f) * 14.0f);
            const int b2 = (int)((s.z + 1.00001f) * 14.0f);
            const int b3 = (int)((s.w + 1.00001f) * 14.0f);
            if (m.x) atomicAdd(&hist[c][warp][b0], 1);
            if (m.y) atomicAdd(&hist[c][warp][b1], 1);
            if (m.z) atomicAdd(&hist[c][warp][b2], 1);
            if (m.w) atomicAdd(&hist[c][warp][b3], 1);
        }

        // Issue slice j+4 into the slot freed at j-1.
        if (j + 4 < NSLICE) {
            const int jn = j + 4;
            const int it = jn / 5, k = jn % 5;
            const void* g = (k == 0) ? (const void*)(gm + it * 256)
                                     : (const void*)(gs + (k - 1) * cStride4 + it * 256);
            cp_async16(rl + (jn % NSLOT) * 512, g);
            CP_COMMIT();
        }
    }
    __syncthreads();

    // reduce 8 warp-copies and write: C*NBINS = 116 outputs per block
    if (t < CDIM * NBINS) {
        const int c   = t / NBINS;
        const int bin = t - c * NBINS;
        int sum = 0;
        #pragma unroll
        for (int w = 0; w < NWARP; ++w) sum += hist[c][w][bin];
        out[(((size_t)b * CDIM + c) * QDIM + q) * NBINS + bin] = (float)sum;
    }
}

extern "C" void kernel_launch(void* const* d_in, const int* in_sizes, int n_in,
                              void* d_out, int out_size)
{
    // sim is 4x larger (element count) than mask; pick by size for robustness.
    int i_sim  = 0, i_mask = 1;
    if (n_in >= 2 && in_sizes[1] > in_sizes[0]) { i_sim = 1; i_mask = 0; }

    const float* sim  = (const float*)d_in[i_sim];    // [B, C, Q, D] float32
    const uint4* mask = (const uint4*)d_in[i_mask];   // [B, Q, D] word-packed bool
    float*       out  = (float*)d_out;                // [B, C, Q, NBINS] float32

    const int blocks = in_sizes[i_mask] / DDIM;       // B*Q = 2048

    count_hist_kernel<<<blocks, 256>>>(sim, mask, out);
}